// round 15
// baseline (speedup 1.0000x reference)
#include <cuda_runtime.h>
#include <cuda_bf16.h>
#include <cstdint>
#include <cstddef>

#define HIDDEN   4096
#define QKV_OUT  6144
#define QSZ      4096
#define KVSZ     1024
#define SLEN     2048
#define NHEADS   32
#define NKV      8
#define HD       128

// ---------------- scratch (device globals; no runtime allocation) ----------------
__device__ float g_qkv [SLEN * QKV_OUT];
__device__ float g_t1  [SLEN * 8];
__device__ float g_t2  [SLEN * 256];
__device__ int   g_flags[4];
__device__ unsigned char g_mask8[SLEN];

// bf16 hi/lo split buffers (all row-major)
__device__ __nv_bfloat16 g_hs_h  [SLEN * HIDDEN],    g_hs_l  [SLEN * HIDDEN];
__device__ __nv_bfloat16 g_wqkv_h[HIDDEN * QKV_OUT], g_wqkv_l[HIDDEN * QKV_OUT];
__device__ __nv_bfloat16 g_wo_h  [QSZ * HIDDEN],     g_wo_l  [QSZ * HIDDEN];
__device__ __nv_bfloat16 g_attn_h[SLEN * QSZ],       g_attn_l[SLEN * QSZ];
__device__ __nv_bfloat16 g_la2_h [QSZ * 256],        g_la2_l [QSZ * 256];
__device__ __nv_bfloat16 g_lb2_h [256 * HIDDEN],     g_lb2_l [256 * HIDDEN];
__device__ __nv_bfloat16 g_t2_h  [SLEN * 256],       g_t2_l  [SLEN * 256];

// ---------------- mask dtype detection + normalization ---------------------------
__global__ void mask_reset_kernel() {
    if (threadIdx.x < 4) g_flags[threadIdx.x] = 0;
}
__global__ void mask_detect_kernel(const unsigned char* __restrict__ m) {
    int r = blockIdx.x * 256 + threadIdx.x;
    unsigned char b = m[r];
    if (b) {
        if ((r & 3) == 0) atomicOr(&g_flags[0], 1);
        else              atomicOr(&g_flags[1], 1);
        if ((r & 7) == 4) atomicOr(&g_flags[2], 1);
    }
}
__global__ void mask_normalize_kernel(const unsigned char* __restrict__ m) {
    int r = blockIdx.x * 256 + threadIdx.x;
    int nz0 = g_flags[0], nz123 = g_flags[1], nz4 = g_flags[2];
    unsigned char v;
    if (nz123 && nz0)      v = (m[r] != 0);
    else if (nz123)        v = (((const float*)m)[r] != 0.0f);
    else if (nz0 && nz4)   v = (((const int*)m)[r] != 0);
    else if (nz0)          v = (((const long long*)m)[r] != 0);
    else                   v = 0;
    g_mask8[r] = v;
}

// ---------------- helpers ---------------------------------------------------------
__device__ __forceinline__ void cvt2(float x, float y, uint32_t& h, uint32_t& l) {
    __nv_bfloat16 hx = __float2bfloat16(x);
    __nv_bfloat16 hy = __float2bfloat16(y);
    __nv_bfloat16 lx = __float2bfloat16(x - __bfloat162float(hx));
    __nv_bfloat16 ly = __float2bfloat16(y - __bfloat162float(hy));
    h = ((uint32_t)__bfloat16_as_ushort(hy) << 16) | __bfloat16_as_ushort(hx);
    l = ((uint32_t)__bfloat16_as_ushort(ly) << 16) | __bfloat16_as_ushort(lx);
}
__device__ __forceinline__ void ldsm_x4(uint32_t* r, uint32_t addr) {
    asm volatile("ldmatrix.sync.aligned.m8n8.x4.shared.b16 {%0,%1,%2,%3},[%4];"
        : "=r"(r[0]), "=r"(r[1]), "=r"(r[2]), "=r"(r[3]) : "r"(addr));
}
__device__ __forceinline__ void ldsm_x2(uint32_t* r, uint32_t addr) {
    asm volatile("ldmatrix.sync.aligned.m8n8.x2.shared.b16 {%0,%1},[%2];"
        : "=r"(r[0]), "=r"(r[1]) : "r"(addr));
}
__device__ __forceinline__ void ldsm_x2t(uint32_t* r, uint32_t addr) {
    asm volatile("ldmatrix.sync.aligned.m8n8.x2.trans.shared.b16 {%0,%1},[%2];"
        : "=r"(r[0]), "=r"(r[1]) : "r"(addr));
}
__device__ __forceinline__ void mma_bf16(float* c, const uint32_t* a, const uint32_t* b) {
    asm volatile("mma.sync.aligned.m16n8k16.row.col.f32.bf16.bf16.f32 "
        "{%0,%1,%2,%3},{%4,%5,%6,%7},{%8,%9},{%0,%1,%2,%3};"
        : "+f"(c[0]), "+f"(c[1]), "+f"(c[2]), "+f"(c[3])
        : "r"(a[0]), "r"(a[1]), "r"(a[2]), "r"(a[3]), "r"(b[0]), "r"(b[1]));
}
__device__ __forceinline__ void cp_async16(uint32_t smem_addr, const void* gptr) {
    asm volatile("cp.async.cg.shared.global [%0], [%1], 16;" :: "r"(smem_addr), "l"(gptr));
}
__device__ __forceinline__ void cp_commit() { asm volatile("cp.async.commit_group;"); }

// ---------------- fp32 -> bf16 hi/lo splitter -------------------------------------
__global__ __launch_bounds__(256) void split_kernel(
    const float* __restrict__ X, __nv_bfloat16* __restrict__ H,
    __nv_bfloat16* __restrict__ L, int n4)
{
    int i = blockIdx.x * 256 + threadIdx.x;
    if (i >= n4) return;
    float4 v = ((const float4*)X)[i];
    uint32_t h0, l0, h1, l1;
    cvt2(v.x, v.y, h0, l0);
    cvt2(v.z, v.w, h1, l1);
    ((uint2*)H)[i] = make_uint2(h0, h1);
    ((uint2*)L)[i] = make_uint2(l0, l1);
}

// ---------------- bf16-pair GEMM, 3-stage cp.async, 2 CTAs/SM ---------------------
#define PA_STRIDE 40
#define PB_STRIDE 136
#define P_AH 0
#define P_AL (128 * PA_STRIDE)
#define P_BH (2 * 128 * PA_STRIDE)
#define P_BL (2 * 128 * PA_STRIDE + 32 * PB_STRIDE)
#define P_STG (2 * 128 * PA_STRIDE + 2 * 32 * PB_STRIDE)   // 18944 bf16 = 37888 B
#define P_SMEM (3 * P_STG * 2)                             // 113664 B (2/SM fits)

template<int MASK_ADD>
__global__ __launch_bounds__(256, 2) void hgemm_bf16(
    const __nv_bfloat16* __restrict__ Ah, const __nv_bfloat16* __restrict__ Al,
    const __nv_bfloat16* __restrict__ Bh, const __nv_bfloat16* __restrict__ Bl,
    float* __restrict__ C, int M, int N, int K,
    float alpha, const unsigned char* __restrict__ mask)
{
    extern __shared__ __nv_bfloat16 sm[];
    int tid  = threadIdx.x;
    int wid  = tid >> 5, lane = tid & 31;
    int wm   = wid >> 2, wn = wid & 3;
    int row0 = blockIdx.y * 128, col0 = blockIdx.x * 128;
    uint32_t sbase = (uint32_t)__cvta_generic_to_shared(sm);
    const int nk = K >> 5;

    float acc[4][4][4];
#pragma unroll
    for (int i = 0; i < 4; i++)
#pragma unroll
        for (int j = 0; j < 4; j++)
#pragma unroll
            for (int k = 0; k < 4; k++) acc[i][j][k] = 0.f;

    auto load_stage = [&](int kt) {
        if (kt < nk) {
            int k0 = kt << 5;
            uint32_t sb = sbase + (uint32_t)(kt % 3) * P_STG * 2;
#pragma unroll
            for (int i = 0; i < 2; i++) {
                int cc = tid + i * 256;
                int r = cc >> 2, c = cc & 3;
                size_t go = (size_t)(row0 + r) * K + k0 + c * 8;
                cp_async16(sb + (uint32_t)(P_AH + r * PA_STRIDE + c * 8) * 2, Ah + go);
                cp_async16(sb + (uint32_t)(P_AL + r * PA_STRIDE + c * 8) * 2, Al + go);
            }
#pragma unroll
            for (int i = 0; i < 2; i++) {
                int cc = tid + i * 256;
                int r = cc >> 4, c = cc & 15;
                size_t go = (size_t)(k0 + r) * N + col0 + c * 8;
                cp_async16(sb + (uint32_t)(P_BH + r * PB_STRIDE + c * 8) * 2, Bh + go);
                cp_async16(sb + (uint32_t)(P_BL + r * PB_STRIDE + c * 8) * 2, Bl + go);
            }
        }
        cp_commit();
    };

    load_stage(0);
    load_stage(1);

    int aRow   = lane & 15;
    int aKhalf = lane >> 4;
    int bKrow  = lane & 15;

    for (int kt = 0; kt < nk; kt++) {
        asm volatile("cp.async.wait_group 1;" ::: "memory");
        __syncthreads();                          // all warps done with stage (kt-1)%3
        load_stage(kt + 2);                       // writes stage (kt+2)%3 == (kt-1)%3

        uint32_t st = sbase + (uint32_t)(kt % 3) * P_STG * 2;
#pragma unroll
        for (int chunk = 0; chunk < 2; chunk++) {
            uint32_t bh[4][2], bl[4][2];
#pragma unroll
            for (int nt = 0; nt < 4; nt++) {
                int kr = chunk * 16 + bKrow;
                uint32_t off = (uint32_t)(kr * PB_STRIDE + wn * 32 + nt * 8) * 2;
                ldsm_x2t(bh[nt], st + P_BH * 2 + off);
                ldsm_x2t(bl[nt], st + P_BL * 2 + off);
            }
#pragma unroll
            for (int mt = 0; mt < 4; mt++) {
                uint32_t ah[4], al[4];
                int row = wm * 64 + mt * 16 + aRow;
                uint32_t off = (uint32_t)(row * PA_STRIDE + chunk * 16) * 2 + aKhalf * 16;
                ldsm_x4(ah, st + P_AH * 2 + off);
                ldsm_x4(al, st + P_AL * 2 + off);
#pragma unroll
                for (int nt = 0; nt < 4; nt++) {
                    mma_bf16(acc[mt][nt], ah, bh[nt]);
                    mma_bf16(acc[mt][nt], ah, bl[nt]);
                    mma_bf16(acc[mt][nt], al, bh[nt]);
                }
            }
        }
    }

#pragma unroll
    for (int mt = 0; mt < 4; mt++) {
#pragma unroll
        for (int nt = 0; nt < 4; nt++) {
            int r = row0 + wm * 64 + mt * 16 + (lane >> 2);
            int c = col0 + wn * 32 + nt * 8 + (lane & 3) * 2;
            float* a = acc[mt][nt];
            if (MASK_ADD) {
                if (!mask[r]) {
                    C[(size_t)r * N + c]     += alpha * a[0];
                    C[(size_t)r * N + c + 1] += alpha * a[1];
                }
                if (!mask[r + 8]) {
                    C[(size_t)(r + 8) * N + c]     += alpha * a[2];
                    C[(size_t)(r + 8) * N + c + 1] += alpha * a[3];
                }
            } else {
                *(float2*)(C + (size_t)r * N + c)       = make_float2(a[0], a[1]);
                *(float2*)(C + (size_t)(r + 8) * N + c) = make_float2(a[2], a[3]);
            }
        }
    }
}

// ---------------- rank-8 LoRA down-proj ------------------------------------------
__global__ __launch_bounds__(256) void lora1_kernel(
    const float* __restrict__ X, const float* __restrict__ LA, float* __restrict__ T1)
{
    int s = blockIdx.x;
    int tid = threadIdx.x;
    float part[8];
#pragma unroll
    for (int r = 0; r < 8; r++) part[r] = 0.f;
    for (int k = tid; k < HIDDEN; k += 256) {
        float x = X[(size_t)s * HIDDEN + k];
        const float* la = LA + (size_t)k * 8;
#pragma unroll
        for (int r = 0; r < 8; r++) part[r] += x * la[r];
    }
    __shared__ float red[8][256];
#pragma unroll
    for (int r = 0; r < 8; r++) red[r][tid] = part[r];
    __syncthreads();
    for (int off = 128; off > 0; off >>= 1) {
        if (tid < off) {
#pragma unroll
            for (int r = 0; r < 8; r++) red[r][tid] += red[r][tid + off];
        }
        __syncthreads();
    }
    if (tid < 8) T1[(size_t)s * 8 + tid] = red[tid][0];
}

// ---------------- qkv += 2.0 * (T1 @ LB) where !mask -----------------------------
__global__ __launch_bounds__(256) void lora_add_qkv_kernel(
    const float* __restrict__ T1, const float* __restrict__ LB,
    float* __restrict__ QKV, const unsigned char* __restrict__ mask)
{
    int s = blockIdx.y;
    if (mask[s]) return;
    __shared__ float t1s[8];
    if (threadIdx.x < 8) t1s[threadIdx.x] = T1[(size_t)s * 8 + threadIdx.x];
    __syncthreads();
    int j = blockIdx.x * 256 + threadIdx.x;
    float sum = 0.f;
#pragma unroll
    for (int r = 0; r < 8; r++) sum += t1s[r] * LB[(size_t)r * QKV_OUT + j];
    QKV[(size_t)s * QKV_OUT + j] += 2.0f * sum;
}

// ---------------- RoPE ------------------------------------------------------------
__global__ __launch_bounds__(256) void rope_kernel(float* __restrict__ QKV)
{
    int s = blockIdx.y;
    int idx = blockIdx.x * 256 + threadIdx.x;
    int h = idx >> 6;
    int d = idx & 63;
    float p = (float)s;
    float inv = expf(-(float)d * (9.210340371976184f / 64.0f));
    float ang = p * inv;
    float c = cosf(ang), sn = sinf(ang);
    float* base = QKV + (size_t)s * QKV_OUT + (size_t)h * HD;
    float x1 = base[d];
    float x2 = base[64 + d];
    base[d]      = x1 * c - x2 * sn;
    base[64 + d] = x2 * c + x1 * sn;
}

// ---------------- flash attention v2 (R13) with LPT scheduling --------------------
#define FQ_STRIDE 136
#define FP_STRIDE 72
#define F_QH 0
#define F_QL (128 * FQ_STRIDE)
#define F_KH (2 * 128 * FQ_STRIDE)
#define F_KL (F_KH + 64 * FQ_STRIDE)
#define F_VH (F_KL + 64 * FQ_STRIDE)
#define F_VL (F_VH + 64 * FQ_STRIDE)
#define F_PH (F_VL + 64 * FQ_STRIDE)
#define F_PL (F_PH + 128 * FP_STRIDE)
#define FLASH_SMEM ((F_PL + 128 * FP_STRIDE) * 2)

__global__ __launch_bounds__(256) void flash_mma_kernel(
    const float* __restrict__ QKV,
    __nv_bfloat16* __restrict__ OH, __nv_bfloat16* __restrict__ OL)
{
    extern __shared__ __nv_bfloat16 sb[];
    __shared__ float sAl[128];
    __shared__ float sLsum[128];
    uint32_t sbase = (uint32_t)__cvta_generic_to_shared(sb);

    int qb  = gridDim.x - 1 - blockIdx.x;   // LPT: longest CTAs launch first
    int h   = blockIdx.y;
    int kvh = h >> 2;
    int tid = threadIdx.x;
    int wid = tid >> 5, lane = tid & 31;
    int q0  = qb * 128;
    int wm  = wid >> 2, wn = wid & 3;

    const float scale = 0.08838834764831845f;

#pragma unroll
    for (int i = 0; i < 16; i++) {
        int lin = tid + i * 256;
        int r = lin >> 5, c4 = lin & 31;
        float4 v = *(const float4*)(QKV + (size_t)(q0 + r) * QKV_OUT + (size_t)h * HD + c4 * 4);
        v.x *= scale; v.y *= scale; v.z *= scale; v.w *= scale;
        uint32_t h0, l0, h1, l1;
        cvt2(v.x, v.y, h0, l0);
        cvt2(v.z, v.w, h1, l1);
        uint32_t* ph = (uint32_t*)(sb + F_QH + r * FQ_STRIDE + c4 * 4);
        uint32_t* pl = (uint32_t*)(sb + F_QL + r * FQ_STRIDE + c4 * 4);
        ph[0] = h0; ph[1] = h1; pl[0] = l0; pl[1] = l1;
    }

    float oacc[4][4][4];
#pragma unroll
    for (int i = 0; i < 4; i++)
#pragma unroll
        for (int j = 0; j < 4; j++)
#pragma unroll
            for (int k = 0; k < 4; k++) oacc[i][j][k] = 0.f;

    float m0 = -1e30f, m1 = -1e30f, lsum0 = 0.f, lsum1 = 0.f;
    int wrow = q0 + wid * 16;
    int gr0  = wrow + (lane >> 2);
    int gr1  = gr0 + 8;

    __syncthreads();

    int ntiles = 2 * qb + 2;
    for (int kt = 0; kt < ntiles; kt++) {
        int k0g = kt * 64;

#pragma unroll
        for (int i = 0; i < 8; i++) {
            int lin = tid + i * 256;
            int r = lin >> 5, c4 = lin & 31;
            const float* kp = QKV + (size_t)(k0g + r) * QKV_OUT + QSZ + (size_t)kvh * HD + c4 * 4;
            float4 kv = *(const float4*)kp;
            uint32_t h0, lo0, h1, lo1;
            cvt2(kv.x, kv.y, h0, lo0);
            cvt2(kv.z, kv.w, h1, lo1);
            uint32_t* ph = (uint32_t*)(sb + F_KH + r * FQ_STRIDE + c4 * 4);
            uint32_t* pl = (uint32_t*)(sb + F_KL + r * FQ_STRIDE + c4 * 4);
            ph[0] = h0; ph[1] = h1; pl[0] = lo0; pl[1] = lo1;
            const float* vp = kp + KVSZ;
            float4 vv = *(const float4*)vp;
            cvt2(vv.x, vv.y, h0, lo0);
            cvt2(vv.z, vv.w, h1, lo1);
            ph = (uint32_t*)(sb + F_VH + r * FQ_STRIDE + c4 * 4);
            pl = (uint32_t*)(sb + F_VL + r * FQ_STRIDE + c4 * 4);
            ph[0] = h0; ph[1] = h1; pl[0] = lo0; pl[1] = lo1;
        }
        __syncthreads();

        if (k0g <= wrow + 15) {
            float sacc[8][4];
#pragma unroll
            for (int i = 0; i < 8; i++)
#pragma unroll
                for (int j = 0; j < 4; j++) sacc[i][j] = 0.f;

#pragma unroll
            for (int kc = 0; kc < 8; kc++) {
                uint32_t ah[4], al[4];
                uint32_t aoff = (uint32_t)((wid * 16 + (lane & 15)) * FQ_STRIDE + kc * 16) * 2 + (lane >> 4) * 16;
                ldsm_x4(ah, sbase + F_QH * 2 + aoff);
                ldsm_x4(al, sbase + F_QL * 2 + aoff);
#pragma unroll
                for (int nt = 0; nt < 8; nt++) {
                    uint32_t bh[2], bl[2];
                    uint32_t boff = (uint32_t)((nt * 8 + (lane & 7)) * FQ_STRIDE + kc * 16) * 2 + ((lane >> 3) & 1) * 16;
                    ldsm_x2(bh, sbase + F_KH * 2 + boff);
                    ldsm_x2(bl, sbase + F_KL * 2 + boff);
                    mma_bf16(sacc[nt], ah, bh);
                    mma_bf16(sacc[nt], ah, bl);
                    mma_bf16(sacc[nt], al, bh);
                }
            }

            float rmax0 = -1e30f, rmax1 = -1e30f;
#pragma unroll
            for (int nt = 0; nt < 8; nt++) {
                int c0 = k0g + nt * 8 + (lane & 3) * 2;
                if (c0 > gr0)     sacc[nt][0] = -1e9f;
                if (c0 + 1 > gr0) sacc[nt][1] = -1e9f;
                if (c0 > gr1)     sacc[nt][2] = -1e9f;
                if (c0 + 1 > gr1) sacc[nt][3] = -1e9f;
                rmax0 = fmaxf(rmax0, fmaxf(sacc[nt][0], sacc[nt][1]));
                rmax1 = fmaxf(rmax1, fmaxf(sacc[nt][2], sacc[nt][3]));
            }
            rmax0 = fmaxf(rmax0, __shfl_xor_sync(0xffffffffu, rmax0, 1));
            rmax0 = fmaxf(rmax0, __shfl_xor_sync(0xffffffffu, rmax0, 2));
            rmax1 = fmaxf(rmax1, __shfl_xor_sync(0xffffffffu, rmax1, 1));
            rmax1 = fmaxf(rmax1, __shfl_xor_sync(0xffffffffu, rmax1, 2));

            float mn0 = fmaxf(m0, rmax0), mn1 = fmaxf(m1, rmax1);
            float al0 = __expf(m0 - mn0), al1 = __expf(m1 - mn1);
            float rs0 = 0.f, rs1 = 0.f;

#pragma unroll
            for (int nt = 0; nt < 8; nt++) {
                float p00 = __expf(sacc[nt][0] - mn0);
                float p01 = __expf(sacc[nt][1] - mn0);
                float p10 = __expf(sacc[nt][2] - mn1);
                float p11 = __expf(sacc[nt][3] - mn1);
                rs0 += p00 + p01;
                rs1 += p10 + p11;
                uint32_t hh0, ll0, hh1, ll1;
                cvt2(p00, p01, hh0, ll0);
                cvt2(p10, p11, hh1, ll1);
                int col = nt * 8 + (lane & 3) * 2;
                int r0l = wid * 16 + (lane >> 2);
                *(uint32_t*)(sb + F_PH + r0l * FP_STRIDE + col)       = hh0;
                *(uint32_t*)(sb + F_PL + r0l * FP_STRIDE + col)       = ll0;
                *(uint32_t*)(sb + F_PH + (r0l + 8) * FP_STRIDE + col) = hh1;
                *(uint32_t*)(sb + F_PL + (r0l + 8) * FP_STRIDE + col) = ll1;
            }
            rs0 += __shfl_xor_sync(0xffffffffu, rs0, 1);
            rs0 += __shfl_xor_sync(0xffffffffu, rs0, 2);
            rs1 += __shfl_xor_sync(0xffffffffu, rs1, 1);
            rs1 += __shfl_xor_sync(0xffffffffu, rs1, 2);

            lsum0 = lsum0 * al0 + rs0;  lsum1 = lsum1 * al1 + rs1;
            m0 = mn0;                   m1 = mn1;

            if ((lane & 3) == 0) {
                sAl[wid * 16 + (lane >> 2)]     = al0;
                sAl[wid * 16 + (lane >> 2) + 8] = al1;
            }
        }
        __syncthreads();

        if (k0g <= q0 + wm * 64 + 63) {
#pragma unroll
            for (int mt = 0; mt < 4; mt++) {
                int rl = wm * 64 + mt * 16 + (lane >> 2);
                float a0 = sAl[rl], a1 = sAl[rl + 8];
#pragma unroll
                for (int nt = 0; nt < 4; nt++) {
                    oacc[mt][nt][0] *= a0; oacc[mt][nt][1] *= a0;
                    oacc[mt][nt][2] *= a1; oacc[mt][nt][3] *= a1;
                }
            }
#pragma unroll
            for (int kc = 0; kc < 4; kc++) {
                uint32_t pah[4][4], pal[4][4];
#pragma unroll
                for (int mt = 0; mt < 4; mt++) {
                    uint32_t aoff = (uint32_t)((wm * 64 + mt * 16 + (lane & 15)) * FP_STRIDE + kc * 16) * 2 + (lane >> 4) * 16;
                    ldsm_x4(pah[mt], sbase + F_PH * 2 + aoff);
                    ldsm_x4(pal[mt], sbase + F_PL * 2 + aoff);
                }
#pragma unroll
                for (int nt = 0; nt < 4; nt++) {
                    uint32_t bh[2], bl[2];
                    uint32_t boff = (uint32_t)((kc * 16 + (lane & 15)) * FQ_STRIDE + wn * 32 + nt * 8) * 2;
                    ldsm_x2t(bh, sbase + F_VH * 2 + boff);
                    ldsm_x2t(bl, sbase + F_VL * 2 + boff);
#pragma unroll
                    for (int mt = 0; mt < 4; mt++) {
                        mma_bf16(oacc[mt][nt], pah[mt], bh);
                        mma_bf16(oacc[mt][nt], pah[mt], bl);
                        mma_bf16(oacc[mt][nt], pal[mt], bh);
                    }
                }
            }
        }
        __syncthreads();
    }

    if ((lane & 3) == 0) {
        sLsum[wid * 16 + (lane >> 2)]     = lsum0;
        sLsum[wid * 16 + (lane >> 2) + 8] = lsum1;
    }
    __syncthreads();

#pragma unroll
    for (int mt = 0; mt < 4; mt++) {
        int rl = wm * 64 + mt * 16 + (lane >> 2);
        float inv0 = 1.f / sLsum[rl];
        float inv1 = 1.f / sLsum[rl + 8];
        int rg0 = q0 + rl, rg1 = rg0 + 8;
#pragma unroll
        for (int nt = 0; nt < 4; nt++) {
            int c = h * HD + wn * 32 + nt * 8 + (lane & 3) * 2;
            uint32_t hb, lb;
            cvt2(oacc[mt][nt][0] * inv0, oacc[mt][nt][1] * inv0, hb, lb);
            *(uint32_t*)(OH + (size_t)rg0 * QSZ + c) = hb;
            *(uint32_t*)(OL + (size_t)rg0 * QSZ + c) = lb;
            cvt2(oacc[mt][nt][2] * inv1, oacc[mt][nt][3] * inv1, hb, lb);
            *(uint32_t*)(OH + (size_t)rg1 * QSZ + c) = hb;
            *(uint32_t*)(OL + (size_t)rg1 * QSZ + c) = lb;
        }
    }
}

// ---------------- launch ----------------------------------------------------------
extern "C" void kernel_launch(void* const* d_in, const int* in_sizes, int n_in,
                              void* d_out, int out_size)
{
    int iMASK, iWQKV, iLA1, iLB1, iWO, iLA2, iLB2;
    if (in_sizes[3] == 25165824) {           // insertion order
        iMASK = 2; iWQKV = 3; iLA1 = 4; iLB1 = 5; iWO = 6; iLA2 = 7; iLB2 = 8;
    } else {                                  // alphabetical order
        iMASK = 1; iLA2 = 3; iLB2 = 4; iWO = 5; iLA1 = 6; iLB1 = 7; iWQKV = 8;
    }

    const float*         hs    = (const float*)d_in[0];
    const unsigned char* maskr = (const unsigned char*)d_in[iMASK];
    const float*         wqkv  = (const float*)d_in[iWQKV];
    const float*         la1   = (const float*)d_in[iLA1];
    const float*         lb1   = (const float*)d_in[iLB1];
    const float*         wo    = (const float*)d_in[iWO];
    const float*         la2   = (const float*)d_in[iLA2];
    const float*         lb2   = (const float*)d_in[iLB2];
    float*               out   = (float*)d_out;

    float *qkv_p, *t1_p, *t2_p;
    unsigned char* mask_p;
    cudaGetSymbolAddress((void**)&qkv_p,  g_qkv);
    cudaGetSymbolAddress((void**)&t1_p,   g_t1);
    cudaGetSymbolAddress((void**)&t2_p,   g_t2);
    cudaGetSymbolAddress((void**)&mask_p, g_mask8);

    __nv_bfloat16 *hs_h, *hs_l, *wqkv_h, *wqkv_l, *wo_h, *wo_l;
    __nv_bfloat16 *attn_h, *attn_l, *la2_h, *la2_l, *lb2_h, *lb2_l, *t2_h, *t2_l;
    cudaGetSymbolAddress((void**)&hs_h,   g_hs_h);   cudaGetSymbolAddress((void**)&hs_l,   g_hs_l);
    cudaGetSymbolAddress((void**)&wqkv_h, g_wqkv_h); cudaGetSymbolAddress((void**)&wqkv_l, g_wqkv_l);
    cudaGetSymbolAddress((void**)&wo_h,   g_wo_h);   cudaGetSymbolAddress((void**)&wo_l,   g_wo_l);
    cudaGetSymbolAddress((void**)&attn_h, g_attn_h); cudaGetSymbolAddress((void**)&attn_l, g_attn_l);
    cudaGetSymbolAddress((void**)&la2_h,  g_la2_h);  cudaGetSymbolAddress((void**)&la2_l,  g_la2_l);
    cudaGetSymbolAddress((void**)&lb2_h,  g_lb2_h);  cudaGetSymbolAddress((void**)&lb2_l,  g_lb2_l);
    cudaGetSymbolAddress((void**)&t2_h,   g_t2_h);   cudaGetSymbolAddress((void**)&t2_l,   g_t2_l);

    cudaFuncSetAttribute(hgemm_bf16<0>, cudaFuncAttributeMaxDynamicSharedMemorySize, P_SMEM);
    cudaFuncSetAttribute(hgemm_bf16<1>, cudaFuncAttributeMaxDynamicSharedMemorySize, P_SMEM);
    cudaFuncSetAttribute(flash_mma_kernel, cudaFuncAttributeMaxDynamicSharedMemorySize, FLASH_SMEM);

    // 0) normalize im_mask
    mask_reset_kernel<<<1, 32>>>();
    mask_detect_kernel<<<SLEN / 256, 256>>>(maskr);
    mask_normalize_kernel<<<SLEN / 256, 256>>>(maskr);

    // 0b) split static operands to bf16 hi/lo
    split_kernel<<<(SLEN * HIDDEN / 4) / 256, 256>>>(hs, hs_h, hs_l, SLEN * HIDDEN / 4);
    split_kernel<<<(HIDDEN * QKV_OUT / 4) / 256, 256>>>(wqkv, wqkv_h, wqkv_l, HIDDEN * QKV_OUT / 4);
    split_kernel<<<(QSZ * HIDDEN / 4) / 256, 256>>>(wo, wo_h, wo_l, QSZ * HIDDEN / 4);
    split_kernel<<<(QSZ * 256 / 4) / 256, 256>>>(la2, la2_h, la2_l, QSZ * 256 / 4);
    split_kernel<<<(256 * HIDDEN / 4) / 256, 256>>>(lb2, lb2_h, lb2_l, 256 * HIDDEN / 4);

    // 1) qkv = hs @ wqkv
    hgemm_bf16<0><<<dim3(QKV_OUT / 128, SLEN / 128), 256, P_SMEM>>>(
        hs_h, hs_l, wqkv_h, wqkv_l, qkv_p, SLEN, QKV_OUT, HIDDEN, 1.f, nullptr);

    // 2) t1 = hs @ la1   (rank 8)
    lora1_kernel<<<SLEN, 256>>>(hs, la1, t1_p);

    // 3) qkv += 2.0 * t1 @ lb1 where !mask
    lora_add_qkv_kernel<<<dim3(QKV_OUT / 256, SLEN), 256>>>(t1_p, lb1, qkv_p, mask_p);

    // 4) RoPE
    rope_kernel<<<dim3((NHEADS + NKV) * 64 / 256, SLEN), 256>>>(qkv_p);

    // 5) flash attention (tensor-core, writes attn hi/lo directly)
    flash_mma_kernel<<<dim3(SLEN / 128, NHEADS), 256, FLASH_SMEM>>>(qkv_p, attn_h, attn_l);

    // 6) out = attn @ wo
    hgemm_bf16<0><<<dim3(HIDDEN / 128, SLEN / 128), 256, P_SMEM>>>(
        attn_h, attn_l, wo_h, wo_l, out, SLEN, HIDDEN, QSZ, 1.f, nullptr);

    // 7) t2 = attn @ la2  (rank 256)
    hgemm_bf16<0><<<dim3(256 / 128, SLEN / 128), 256, P_SMEM>>>(
        attn_h, attn_l, la2_h, la2_l, t2_p, SLEN, 256, QSZ, 1.f, nullptr);

    // 7b) split t2
    split_kernel<<<(SLEN * 256 / 4) / 256, 256>>>(t2_p, t2_h, t2_l, SLEN * 256 / 4);

    // 8) out += t2 @ lb2 where !mask
    hgemm_bf16<1><<<dim3(HIDDEN / 128, SLEN / 128), 256, P_SMEM>>>(
        t2_h, t2_l, lb2_h, lb2_l, out, SLEN, HIDDEN, 256, 1.0f, mask_p);
}

// round 17
// speedup vs baseline: 1.0271x; 1.0271x over previous
#include <cuda_runtime.h>
#include <cuda_bf16.h>
#include <cstdint>
#include <cstddef>

#define HIDDEN   4096
#define QKV_OUT  6144
#define QSZ      4096
#define KVSZ     1024
#define SLEN     2048
#define NHEADS   32
#define NKV      8
#define HD       128

// ---------------- scratch (device globals; no runtime allocation) ----------------
__device__ float g_qkv [SLEN * QKV_OUT];
__device__ float g_t1  [SLEN * 8];
__device__ float g_t2  [SLEN * 256];
__device__ int   g_flags[4];
__device__ unsigned char g_mask8[SLEN];

// bf16 hi/lo split buffers (all row-major)
__device__ __nv_bfloat16 g_hs_h  [SLEN * HIDDEN],    g_hs_l  [SLEN * HIDDEN];
__device__ __nv_bfloat16 g_wqkv_h[HIDDEN * QKV_OUT], g_wqkv_l[HIDDEN * QKV_OUT];
__device__ __nv_bfloat16 g_wo_h  [QSZ * HIDDEN],     g_wo_l  [QSZ * HIDDEN];
__device__ __nv_bfloat16 g_attn_h[SLEN * QSZ],       g_attn_l[SLEN * QSZ];
__device__ __nv_bfloat16 g_la2_h [QSZ * 256],        g_la2_l [QSZ * 256];
__device__ __nv_bfloat16 g_lb2_h [256 * HIDDEN],     g_lb2_l [256 * HIDDEN];
__device__ __nv_bfloat16 g_t2_h  [SLEN * 256],       g_t2_l  [SLEN * 256];

// ---------------- mask dtype detection + normalization ---------------------------
__global__ void mask_reset_kernel() {
    if (threadIdx.x < 4) g_flags[threadIdx.x] = 0;
}
__global__ void mask_detect_kernel(const unsigned char* __restrict__ m) {
    int r = blockIdx.x * 256 + threadIdx.x;
    unsigned char b = m[r];
    if (b) {
        if ((r & 3) == 0) atomicOr(&g_flags[0], 1);
        else              atomicOr(&g_flags[1], 1);
        if ((r & 7) == 4) atomicOr(&g_flags[2], 1);
    }
}
__global__ void mask_normalize_kernel(const unsigned char* __restrict__ m) {
    int r = blockIdx.x * 256 + threadIdx.x;
    int nz0 = g_flags[0], nz123 = g_flags[1], nz4 = g_flags[2];
    unsigned char v;
    if (nz123 && nz0)      v = (m[r] != 0);
    else if (nz123)        v = (((const float*)m)[r] != 0.0f);
    else if (nz0 && nz4)   v = (((const int*)m)[r] != 0);
    else if (nz0)          v = (((const long long*)m)[r] != 0);
    else                   v = 0;
    g_mask8[r] = v;
}

// ---------------- helpers ---------------------------------------------------------
__device__ __forceinline__ void cvt2(float x, float y, uint32_t& h, uint32_t& l) {
    __nv_bfloat16 hx = __float2bfloat16(x);
    __nv_bfloat16 hy = __float2bfloat16(y);
    __nv_bfloat16 lx = __float2bfloat16(x - __bfloat162float(hx));
    __nv_bfloat16 ly = __float2bfloat16(y - __bfloat162float(hy));
    h = ((uint32_t)__bfloat16_as_ushort(hy) << 16) | __bfloat16_as_ushort(hx);
    l = ((uint32_t)__bfloat16_as_ushort(ly) << 16) | __bfloat16_as_ushort(lx);
}
__device__ __forceinline__ void ldsm_x4(uint32_t* r, uint32_t addr) {
    asm volatile("ldmatrix.sync.aligned.m8n8.x4.shared.b16 {%0,%1,%2,%3},[%4];"
        : "=r"(r[0]), "=r"(r[1]), "=r"(r[2]), "=r"(r[3]) : "r"(addr));
}
__device__ __forceinline__ void ldsm_x2(uint32_t* r, uint32_t addr) {
    asm volatile("ldmatrix.sync.aligned.m8n8.x2.shared.b16 {%0,%1},[%2];"
        : "=r"(r[0]), "=r"(r[1]) : "r"(addr));
}
__device__ __forceinline__ void ldsm_x2t(uint32_t* r, uint32_t addr) {
    asm volatile("ldmatrix.sync.aligned.m8n8.x2.trans.shared.b16 {%0,%1},[%2];"
        : "=r"(r[0]), "=r"(r[1]) : "r"(addr));
}
__device__ __forceinline__ void mma_bf16(float* c, const uint32_t* a, const uint32_t* b) {
    asm volatile("mma.sync.aligned.m16n8k16.row.col.f32.bf16.bf16.f32 "
        "{%0,%1,%2,%3},{%4,%5,%6,%7},{%8,%9},{%0,%1,%2,%3};"
        : "+f"(c[0]), "+f"(c[1]), "+f"(c[2]), "+f"(c[3])
        : "r"(a[0]), "r"(a[1]), "r"(a[2]), "r"(a[3]), "r"(b[0]), "r"(b[1]));
}
__device__ __forceinline__ void cp_async16(uint32_t smem_addr, const void* gptr) {
    asm volatile("cp.async.cg.shared.global [%0], [%1], 16;" :: "r"(smem_addr), "l"(gptr));
}
__device__ __forceinline__ void cp_commit() { asm volatile("cp.async.commit_group;"); }

// ---------------- fp32 -> bf16 hi/lo splitter -------------------------------------
__global__ __launch_bounds__(256) void split_kernel(
    const float* __restrict__ X, __nv_bfloat16* __restrict__ H,
    __nv_bfloat16* __restrict__ L, int n4)
{
    int i = blockIdx.x * 256 + threadIdx.x;
    if (i >= n4) return;
    float4 v = ((const float4*)X)[i];
    uint32_t h0, l0, h1, l1;
    cvt2(v.x, v.y, h0, l0);
    cvt2(v.z, v.w, h1, l1);
    ((uint2*)H)[i] = make_uint2(h0, h1);
    ((uint2*)L)[i] = make_uint2(l0, l1);
}

// ---------------- bf16-pair GEMM, 2-stage cp.async, 2 CTAs/SM (R14 proven) --------
#define PA_STRIDE 40
#define PB_STRIDE 136
#define P_AH 0
#define P_AL (128 * PA_STRIDE)
#define P_BH (2 * 128 * PA_STRIDE)
#define P_BL (2 * 128 * PA_STRIDE + 32 * PB_STRIDE)
#define P_STG (2 * 128 * PA_STRIDE + 2 * 32 * PB_STRIDE)   // 18944 bf16 = 37888 B
#define P_SMEM (2 * P_STG * 2)                             // 75776 B

template<int MASK_ADD>
__global__ __launch_bounds__(256, 2) void hgemm_bf16(
    const __nv_bfloat16* __restrict__ Ah, const __nv_bfloat16* __restrict__ Al,
    const __nv_bfloat16* __restrict__ Bh, const __nv_bfloat16* __restrict__ Bl,
    float* __restrict__ C, int M, int N, int K,
    float alpha, const unsigned char* __restrict__ mask)
{
    extern __shared__ __nv_bfloat16 sm[];
    int tid  = threadIdx.x;
    int wid  = tid >> 5, lane = tid & 31;
    int wm   = wid >> 2, wn = wid & 3;
    int row0 = blockIdx.y * 128, col0 = blockIdx.x * 128;
    uint32_t sbase = (uint32_t)__cvta_generic_to_shared(sm);
    const int nk = K >> 5;

    float acc[4][4][4];
#pragma unroll
    for (int i = 0; i < 4; i++)
#pragma unroll
        for (int j = 0; j < 4; j++)
#pragma unroll
            for (int k = 0; k < 4; k++) acc[i][j][k] = 0.f;

    auto load_stage = [&](int kt) {
        if (kt < nk) {
            int k0 = kt << 5;
            uint32_t sb = sbase + (uint32_t)(kt & 1) * P_STG * 2;
#pragma unroll
            for (int i = 0; i < 2; i++) {
                int cc = tid + i * 256;
                int r = cc >> 2, c = cc & 3;
                size_t go = (size_t)(row0 + r) * K + k0 + c * 8;
                cp_async16(sb + (uint32_t)(P_AH + r * PA_STRIDE + c * 8) * 2, Ah + go);
                cp_async16(sb + (uint32_t)(P_AL + r * PA_STRIDE + c * 8) * 2, Al + go);
            }
#pragma unroll
            for (int i = 0; i < 2; i++) {
                int cc = tid + i * 256;
                int r = cc >> 4, c = cc & 15;
                size_t go = (size_t)(k0 + r) * N + col0 + c * 8;
                cp_async16(sb + (uint32_t)(P_BH + r * PB_STRIDE + c * 8) * 2, Bh + go);
                cp_async16(sb + (uint32_t)(P_BL + r * PB_STRIDE + c * 8) * 2, Bl + go);
            }
        }
        cp_commit();
    };

    load_stage(0);

    int aRow   = lane & 15;
    int aKhalf = lane >> 4;
    int bKrow  = lane & 15;

    for (int kt = 0; kt < nk; kt++) {
        asm volatile("cp.async.wait_group 0;" ::: "memory");
        __syncthreads();                 // orders prior compute + this load's visibility
        load_stage(kt + 1);              // overlaps with compute below

        uint32_t st = sbase + (uint32_t)(kt & 1) * P_STG * 2;
#pragma unroll
        for (int chunk = 0; chunk < 2; chunk++) {
            uint32_t bh[4][2], bl[4][2];
#pragma unroll
            for (int nt = 0; nt < 4; nt++) {
                int kr = chunk * 16 + bKrow;
                uint32_t off = (uint32_t)(kr * PB_STRIDE + wn * 32 + nt * 8) * 2;
                ldsm_x2t(bh[nt], st + P_BH * 2 + off);
                ldsm_x2t(bl[nt], st + P_BL * 2 + off);
            }
#pragma unroll
            for (int mt = 0; mt < 4; mt++) {
                uint32_t ah[4], al[4];
                int row = wm * 64 + mt * 16 + aRow;
                uint32_t off = (uint32_t)(row * PA_STRIDE + chunk * 16) * 2 + aKhalf * 16;
                ldsm_x4(ah, st + P_AH * 2 + off);
                ldsm_x4(al, st + P_AL * 2 + off);
#pragma unroll
                for (int nt = 0; nt < 4; nt++) {
                    mma_bf16(acc[mt][nt], ah, bh[nt]);
                    mma_bf16(acc[mt][nt], ah, bl[nt]);
                    mma_bf16(acc[mt][nt], al, bh[nt]);
                }
            }
        }
        // NOTE: no bottom barrier — next iteration's wait_group 0 + __syncthreads
        // orders all warps' compute(kt) before load_stage(kt+2) reuses this buffer.
    }

#pragma unroll
    for (int mt = 0; mt < 4; mt++) {
#pragma unroll
        for (int nt = 0; nt < 4; nt++) {
            int r = row0 + wm * 64 + mt * 16 + (lane >> 2);
            int c = col0 + wn * 32 + nt * 8 + (lane & 3) * 2;
            float* a = acc[mt][nt];
            if (MASK_ADD) {
                if (!mask[r]) {
                    C[(size_t)r * N + c]     += alpha * a[0];
                    C[(size_t)r * N + c + 1] += alpha * a[1];
                }
                if (!mask[r + 8]) {
                    C[(size_t)(r + 8) * N + c]     += alpha * a[2];
                    C[(size_t)(r + 8) * N + c + 1] += alpha * a[3];
                }
            } else {
                *(float2*)(C + (size_t)r * N + c)       = make_float2(a[0], a[1]);
                *(float2*)(C + (size_t)(r + 8) * N + c) = make_float2(a[2], a[3]);
            }
        }
    }
}

// ---------------- rank-8 LoRA down-proj ------------------------------------------
__global__ __launch_bounds__(256) void lora1_kernel(
    const float* __restrict__ X, const float* __restrict__ LA, float* __restrict__ T1)
{
    int s = blockIdx.x;
    int tid = threadIdx.x;
    float part[8];
#pragma unroll
    for (int r = 0; r < 8; r++) part[r] = 0.f;
    for (int k = tid; k < HIDDEN; k += 256) {
        float x = X[(size_t)s * HIDDEN + k];
        const float* la = LA + (size_t)k * 8;
#pragma unroll
        for (int r = 0; r < 8; r++) part[r] += x * la[r];
    }
    __shared__ float red[8][256];
#pragma unroll
    for (int r = 0; r < 8; r++) red[r][tid] = part[r];
    __syncthreads();
    for (int off = 128; off > 0; off >>= 1) {
        if (tid < off) {
#pragma unroll
            for (int r = 0; r < 8; r++) red[r][tid] += red[r][tid + off];
        }
        __syncthreads();
    }
    if (tid < 8) T1[(size_t)s * 8 + tid] = red[tid][0];
}

// ---------------- qkv += 2.0 * (T1 @ LB) where !mask -----------------------------
__global__ __launch_bounds__(256) void lora_add_qkv_kernel(
    const float* __restrict__ T1, const float* __restrict__ LB,
    float* __restrict__ QKV, const unsigned char* __restrict__ mask)
{
    int s = blockIdx.y;
    if (mask[s]) return;
    __shared__ float t1s[8];
    if (threadIdx.x < 8) t1s[threadIdx.x] = T1[(size_t)s * 8 + threadIdx.x];
    __syncthreads();
    int j = blockIdx.x * 256 + threadIdx.x;
    float sum = 0.f;
#pragma unroll
    for (int r = 0; r < 8; r++) sum += t1s[r] * LB[(size_t)r * QKV_OUT + j];
    QKV[(size_t)s * QKV_OUT + j] += 2.0f * sum;
}

// ---------------- RoPE ------------------------------------------------------------
__global__ __launch_bounds__(256) void rope_kernel(float* __restrict__ QKV)
{
    int s = blockIdx.y;
    int idx = blockIdx.x * 256 + threadIdx.x;
    int h = idx >> 6;
    int d = idx & 63;
    float p = (float)s;
    float inv = expf(-(float)d * (9.210340371976184f / 64.0f));
    float ang = p * inv;
    float c = cosf(ang), sn = sinf(ang);
    float* base = QKV + (size_t)s * QKV_OUT + (size_t)h * HD;
    float x1 = base[d];
    float x2 = base[64 + d];
    base[d]      = x1 * c - x2 * sn;
    base[64 + d] = x2 * c + x1 * sn;
}

// ---------------- flash attention v2 (R13) with LPT scheduling --------------------
#define FQ_STRIDE 136
#define FP_STRIDE 72
#define F_QH 0
#define F_QL (128 * FQ_STRIDE)
#define F_KH (2 * 128 * FQ_STRIDE)
#define F_KL (F_KH + 64 * FQ_STRIDE)
#define F_VH (F_KL + 64 * FQ_STRIDE)
#define F_VL (F_VH + 64 * FQ_STRIDE)
#define F_PH (F_VL + 64 * FQ_STRIDE)
#define F_PL (F_PH + 128 * FP_STRIDE)
#define FLASH_SMEM ((F_PL + 128 * FP_STRIDE) * 2)

__global__ __launch_bounds__(256) void flash_mma_kernel(
    const float* __restrict__ QKV,
    __nv_bfloat16* __restrict__ OH, __nv_bfloat16* __restrict__ OL)
{
    extern __shared__ __nv_bfloat16 sb[];
    __shared__ float sAl[128];
    __shared__ float sLsum[128];
    uint32_t sbase = (uint32_t)__cvta_generic_to_shared(sb);

    int qb  = gridDim.x - 1 - blockIdx.x;   // LPT: longest CTAs launch first
    int h   = blockIdx.y;
    int kvh = h >> 2;
    int tid = threadIdx.x;
    int wid = tid >> 5, lane = tid & 31;
    int q0  = qb * 128;
    int wm  = wid >> 2, wn = wid & 3;

    const float scale = 0.08838834764831845f;

#pragma unroll
    for (int i = 0; i < 16; i++) {
        int lin = tid + i * 256;
        int r = lin >> 5, c4 = lin & 31;
        float4 v = *(const float4*)(QKV + (size_t)(q0 + r) * QKV_OUT + (size_t)h * HD + c4 * 4);
        v.x *= scale; v.y *= scale; v.z *= scale; v.w *= scale;
        uint32_t h0, l0, h1, l1;
        cvt2(v.x, v.y, h0, l0);
        cvt2(v.z, v.w, h1, l1);
        uint32_t* ph = (uint32_t*)(sb + F_QH + r * FQ_STRIDE + c4 * 4);
        uint32_t* pl = (uint32_t*)(sb + F_QL + r * FQ_STRIDE + c4 * 4);
        ph[0] = h0; ph[1] = h1; pl[0] = l0; pl[1] = l1;
    }

    float oacc[4][4][4];
#pragma unroll
    for (int i = 0; i < 4; i++)
#pragma unroll
        for (int j = 0; j < 4; j++)
#pragma unroll
            for (int k = 0; k < 4; k++) oacc[i][j][k] = 0.f;

    float m0 = -1e30f, m1 = -1e30f, lsum0 = 0.f, lsum1 = 0.f;
    int wrow = q0 + wid * 16;
    int gr0  = wrow + (lane >> 2);
    int gr1  = gr0 + 8;

    __syncthreads();

    int ntiles = 2 * qb + 2;
    for (int kt = 0; kt < ntiles; kt++) {
        int k0g = kt * 64;

#pragma unroll
        for (int i = 0; i < 8; i++) {
            int lin = tid + i * 256;
            int r = lin >> 5, c4 = lin & 31;
            const float* kp = QKV + (size_t)(k0g + r) * QKV_OUT + QSZ + (size_t)kvh * HD + c4 * 4;
            float4 kv = *(const float4*)kp;
            uint32_t h0, lo0, h1, lo1;
            cvt2(kv.x, kv.y, h0, lo0);
            cvt2(kv.z, kv.w, h1, lo1);
            uint32_t* ph = (uint32_t*)(sb + F_KH + r * FQ_STRIDE + c4 * 4);
            uint32_t* pl = (uint32_t*)(sb + F_KL + r * FQ_STRIDE + c4 * 4);
            ph[0] = h0; ph[1] = h1; pl[0] = lo0; pl[1] = lo1;
            const float* vp = kp + KVSZ;
            float4 vv = *(const float4*)vp;
            cvt2(vv.x, vv.y, h0, lo0);
            cvt2(vv.z, vv.w, h1, lo1);
            ph = (uint32_t*)(sb + F_VH + r * FQ_STRIDE + c4 * 4);
            pl = (uint32_t*)(sb + F_VL + r * FQ_STRIDE + c4 * 4);
            ph[0] = h0; ph[1] = h1; pl[0] = lo0; pl[1] = lo1;
        }
        __syncthreads();

        if (k0g <= wrow + 15) {
            float sacc[8][4];
#pragma unroll
            for (int i = 0; i < 8; i++)
#pragma unroll
                for (int j = 0; j < 4; j++) sacc[i][j] = 0.f;

#pragma unroll
            for (int kc = 0; kc < 8; kc++) {
                uint32_t ah[4], al[4];
                uint32_t aoff = (uint32_t)((wid * 16 + (lane & 15)) * FQ_STRIDE + kc * 16) * 2 + (lane >> 4) * 16;
                ldsm_x4(ah, sbase + F_QH * 2 + aoff);
                ldsm_x4(al, sbase + F_QL * 2 + aoff);
#pragma unroll
                for (int nt = 0; nt < 8; nt++) {
                    uint32_t bh[2], bl[2];
                    uint32_t boff = (uint32_t)((nt * 8 + (lane & 7)) * FQ_STRIDE + kc * 16) * 2 + ((lane >> 3) & 1) * 16;
                    ldsm_x2(bh, sbase + F_KH * 2 + boff);
                    ldsm_x2(bl, sbase + F_KL * 2 + boff);
                    mma_bf16(sacc[nt], ah, bh);
                    mma_bf16(sacc[nt], ah, bl);
                    mma_bf16(sacc[nt], al, bh);
                }
            }

            float rmax0 = -1e30f, rmax1 = -1e30f;
#pragma unroll
            for (int nt = 0; nt < 8; nt++) {
                int c0 = k0g + nt * 8 + (lane & 3) * 2;
                if (c0 > gr0)     sacc[nt][0] = -1e9f;
                if (c0 + 1 > gr0) sacc[nt][1] = -1e9f;
                if (c0 > gr1)     sacc[nt][2] = -1e9f;
                if (c0 + 1 > gr1) sacc[nt][3] = -1e9f;
                rmax0 = fmaxf(rmax0, fmaxf(sacc[nt][0], sacc[nt][1]));
                rmax1 = fmaxf(rmax1, fmaxf(sacc[nt][2], sacc[nt][3]));
            }
            rmax0 = fmaxf(rmax0, __shfl_xor_sync(0xffffffffu, rmax0, 1));
            rmax0 = fmaxf(rmax0, __shfl_xor_sync(0xffffffffu, rmax0, 2));
            rmax1 = fmaxf(rmax1, __shfl_xor_sync(0xffffffffu, rmax1, 1));
            rmax1 = fmaxf(rmax1, __shfl_xor_sync(0xffffffffu, rmax1, 2));

            float mn0 = fmaxf(m0, rmax0), mn1 = fmaxf(m1, rmax1);
            float al0 = __expf(m0 - mn0), al1 = __expf(m1 - mn1);
            float rs0 = 0.f, rs1 = 0.f;

#pragma unroll
            for (int nt = 0; nt < 8; nt++) {
                float p00 = __expf(sacc[nt][0] - mn0);
                float p01 = __expf(sacc[nt][1] - mn0);
                float p10 = __expf(sacc[nt][2] - mn1);
                float p11 = __expf(sacc[nt][3] - mn1);
                rs0 += p00 + p01;
                rs1 += p10 + p11;
                uint32_t hh0, ll0, hh1, ll1;
                cvt2(p00, p01, hh0, ll0);
                cvt2(p10, p11, hh1, ll1);
                int col = nt * 8 + (lane & 3) * 2;
                int r0l = wid * 16 + (lane >> 2);
                *(uint32_t*)(sb + F_PH + r0l * FP_STRIDE + col)       = hh0;
                *(uint32_t*)(sb + F_PL + r0l * FP_STRIDE + col)       = ll0;
                *(uint32_t*)(sb + F_PH + (r0l + 8) * FP_STRIDE + col) = hh1;
                *(uint32_t*)(sb + F_PL + (r0l + 8) * FP_STRIDE + col) = ll1;
            }
            rs0 += __shfl_xor_sync(0xffffffffu, rs0, 1);
            rs0 += __shfl_xor_sync(0xffffffffu, rs0, 2);
            rs1 += __shfl_xor_sync(0xffffffffu, rs1, 1);
            rs1 += __shfl_xor_sync(0xffffffffu, rs1, 2);

            lsum0 = lsum0 * al0 + rs0;  lsum1 = lsum1 * al1 + rs1;
            m0 = mn0;                   m1 = mn1;

            if ((lane & 3) == 0) {
                sAl[wid * 16 + (lane >> 2)]     = al0;
                sAl[wid * 16 + (lane >> 2) + 8] = al1;
            }
        }
        __syncthreads();

        if (k0g <= q0 + wm * 64 + 63) {
#pragma unroll
            for (int mt = 0; mt < 4; mt++) {
                int rl = wm * 64 + mt * 16 + (lane >> 2);
                float a0 = sAl[rl], a1 = sAl[rl + 8];
#pragma unroll
                for (int nt = 0; nt < 4; nt++) {
                    oacc[mt][nt][0] *= a0; oacc[mt][nt][1] *= a0;
                    oacc[mt][nt][2] *= a1; oacc[mt][nt][3] *= a1;
                }
            }
#pragma unroll
            for (int kc = 0; kc < 4; kc++) {
                uint32_t pah[4][4], pal[4][4];
#pragma unroll
                for (int mt = 0; mt < 4; mt++) {
                    uint32_t aoff = (uint32_t)((wm * 64 + mt * 16 + (lane & 15)) * FP_STRIDE + kc * 16) * 2 + (lane >> 4) * 16;
                    ldsm_x4(pah[mt], sbase + F_PH * 2 + aoff);
                    ldsm_x4(pal[mt], sbase + F_PL * 2 + aoff);
                }
#pragma unroll
                for (int nt = 0; nt < 4; nt++) {
                    uint32_t bh[2], bl[2];
                    uint32_t boff = (uint32_t)((kc * 16 + (lane & 15)) * FQ_STRIDE + wn * 32 + nt * 8) * 2;
                    ldsm_x2t(bh, sbase + F_VH * 2 + boff);
                    ldsm_x2t(bl, sbase + F_VL * 2 + boff);
#pragma unroll
                    for (int mt = 0; mt < 4; mt++) {
                        mma_bf16(oacc[mt][nt], pah[mt], bh);
                        mma_bf16(oacc[mt][nt], pah[mt], bl);
                        mma_bf16(oacc[mt][nt], pal[mt], bh);
                    }
                }
            }
        }
        __syncthreads();
    }

    if ((lane & 3) == 0) {
        sLsum[wid * 16 + (lane >> 2)]     = lsum0;
        sLsum[wid * 16 + (lane >> 2) + 8] = lsum1;
    }
    __syncthreads();

#pragma unroll
    for (int mt = 0; mt < 4; mt++) {
        int rl = wm * 64 + mt * 16 + (lane >> 2);
        float inv0 = 1.f / sLsum[rl];
        float inv1 = 1.f / sLsum[rl + 8];
        int rg0 = q0 + rl, rg1 = rg0 + 8;
#pragma unroll
        for (int nt = 0; nt < 4; nt++) {
            int c = h * HD + wn * 32 + nt * 8 + (lane & 3) * 2;
            uint32_t hb, lb;
            cvt2(oacc[mt][nt][0] * inv0, oacc[mt][nt][1] * inv0, hb, lb);
            *(uint32_t*)(OH + (size_t)rg0 * QSZ + c) = hb;
            *(uint32_t*)(OL + (size_t)rg0 * QSZ + c) = lb;
            cvt2(oacc[mt][nt][2] * inv1, oacc[mt][nt][3] * inv1, hb, lb);
            *(uint32_t*)(OH + (size_t)rg1 * QSZ + c) = hb;
            *(uint32_t*)(OL + (size_t)rg1 * QSZ + c) = lb;
        }
    }
}

// ---------------- launch ----------------------------------------------------------
extern "C" void kernel_launch(void* const* d_in, const int* in_sizes, int n_in,
                              void* d_out, int out_size)
{
    int iMASK, iWQKV, iLA1, iLB1, iWO, iLA2, iLB2;
    if (in_sizes[3] == 25165824) {           // insertion order
        iMASK = 2; iWQKV = 3; iLA1 = 4; iLB1 = 5; iWO = 6; iLA2 = 7; iLB2 = 8;
    } else {                                  // alphabetical order
        iMASK = 1; iLA2 = 3; iLB2 = 4; iWO = 5; iLA1 = 6; iLB1 = 7; iWQKV = 8;
    }

    const float*         hs    = (const float*)d_in[0];
    const unsigned char* maskr = (const unsigned char*)d_in[iMASK];
    const float*         wqkv  = (const float*)d_in[iWQKV];
    const float*         la1   = (const float*)d_in[iLA1];
    const float*         lb1   = (const float*)d_in[iLB1];
    const float*         wo    = (const float*)d_in[iWO];
    const float*         la2   = (const float*)d_in[iLA2];
    const float*         lb2   = (const float*)d_in[iLB2];
    float*               out   = (float*)d_out;

    float *qkv_p, *t1_p, *t2_p;
    unsigned char* mask_p;
    cudaGetSymbolAddress((void**)&qkv_p,  g_qkv);
    cudaGetSymbolAddress((void**)&t1_p,   g_t1);
    cudaGetSymbolAddress((void**)&t2_p,   g_t2);
    cudaGetSymbolAddress((void**)&mask_p, g_mask8);

    __nv_bfloat16 *hs_h, *hs_l, *wqkv_h, *wqkv_l, *wo_h, *wo_l;
    __nv_bfloat16 *attn_h, *attn_l, *la2_h, *la2_l, *lb2_h, *lb2_l, *t2_h, *t2_l;
    cudaGetSymbolAddress((void**)&hs_h,   g_hs_h);   cudaGetSymbolAddress((void**)&hs_l,   g_hs_l);
    cudaGetSymbolAddress((void**)&wqkv_h, g_wqkv_h); cudaGetSymbolAddress((void**)&wqkv_l, g_wqkv_l);
    cudaGetSymbolAddress((void**)&wo_h,   g_wo_h);   cudaGetSymbolAddress((void**)&wo_l,   g_wo_l);
    cudaGetSymbolAddress((void**)&attn_h, g_attn_h); cudaGetSymbolAddress((void**)&attn_l, g_attn_l);
    cudaGetSymbolAddress((void**)&la2_h,  g_la2_h);  cudaGetSymbolAddress((void**)&la2_l,  g_la2_l);
    cudaGetSymbolAddress((void**)&lb2_h,  g_lb2_h);  cudaGetSymbolAddress((void**)&lb2_l,  g_lb2_l);
    cudaGetSymbolAddress((void**)&t2_h,   g_t2_h);   cudaGetSymbolAddress((void**)&t2_l,   g_t2_l);

    cudaFuncSetAttribute(hgemm_bf16<0>, cudaFuncAttributeMaxDynamicSharedMemorySize, P_SMEM);
    cudaFuncSetAttribute(hgemm_bf16<1>, cudaFuncAttributeMaxDynamicSharedMemorySize, P_SMEM);
    cudaFuncSetAttribute(flash_mma_kernel, cudaFuncAttributeMaxDynamicSharedMemorySize, FLASH_SMEM);

    // 0) normalize im_mask
    mask_reset_kernel<<<1, 32>>>();
    mask_detect_kernel<<<SLEN / 256, 256>>>(maskr);
    mask_normalize_kernel<<<SLEN / 256, 256>>>(maskr);

    // 0b) split static operands to bf16 hi/lo
    split_kernel<<<(SLEN * HIDDEN / 4) / 256, 256>>>(hs, hs_h, hs_l, SLEN * HIDDEN / 4);
    split_kernel<<<(HIDDEN * QKV_OUT / 4) / 256, 256>>>(wqkv, wqkv_h, wqkv_l, HIDDEN * QKV_OUT / 4);
    split_kernel<<<(QSZ * HIDDEN / 4) / 256, 256>>>(wo, wo_h, wo_l, QSZ * HIDDEN / 4);
    split_kernel<<<(QSZ * 256 / 4) / 256, 256>>>(la2, la2_h, la2_l, QSZ * 256 / 4);
    split_kernel<<<(256 * HIDDEN / 4) / 256, 256>>>(lb2, lb2_h, lb2_l, 256 * HIDDEN / 4);

    // 1) qkv = hs @ wqkv
    hgemm_bf16<0><<<dim3(QKV_OUT / 128, SLEN / 128), 256, P_SMEM>>>(
        hs_h, hs_l, wqkv_h, wqkv_l, qkv_p, SLEN, QKV_OUT, HIDDEN, 1.f, nullptr);

    // 2) t1 = hs @ la1   (rank 8)
    lora1_kernel<<<SLEN, 256>>>(hs, la1, t1_p);

    // 3) qkv += 2.0 * t1 @ lb1 where !mask
    lora_add_qkv_kernel<<<dim3(QKV_OUT / 256, SLEN), 256>>>(t1_p, lb1, qkv_p, mask_p);

    // 4) RoPE
    rope_kernel<<<dim3((NHEADS + NKV) * 64 / 256, SLEN), 256>>>(qkv_p);

    // 5) flash attention (tensor-core, writes attn hi/lo directly)
    flash_mma_kernel<<<dim3(SLEN / 128, NHEADS), 256, FLASH_SMEM>>>(qkv_p, attn_h, attn_l);

    // 6) out = attn @ wo
    hgemm_bf16<0><<<dim3(HIDDEN / 128, SLEN / 128), 256, P_SMEM>>>(
        attn_h, attn_l, wo_h, wo_l, out, SLEN, HIDDEN, QSZ, 1.f, nullptr);

    // 7) t2 = attn @ la2  (rank 256)
    hgemm_bf16<0><<<dim3(256 / 128, SLEN / 128), 256, P_SMEM>>>(
        attn_h, attn_l, la2_h, la2_l, t2_p, SLEN, 256, QSZ, 1.f, nullptr);

    // 7b) split t2
    split_kernel<<<(SLEN * 256 / 4) / 256, 256>>>(t2_p, t2_h, t2_l, SLEN * 256 / 4);

    // 8) out += t2 @ lb2 where !mask
    hgemm_bf16<1><<<dim3(HIDDEN / 128, SLEN / 128), 256, P_SMEM>>>(
        t2_h, t2_l, lb2_h, lb2_l, out, SLEN, HIDDEN, 256, 1.0f, mask_p);
}